// round 1
// baseline (speedup 1.0000x reference)
#include <cuda_runtime.h>
#include <math.h>

// Problem shapes (fixed by the dataset)
#define B_ROWS 16384
#define DK     512
#define NKEYS  4096
#define DV     512
#define NH     32
#define TAU_MIN 0.1f
#define TAU_MAX 5.0f
#define EPSF    1e-8f

// Scratch: scaled logits (268 MB), per-row max and tau.
__device__ float g_logits[(size_t)B_ROWS * NKEYS];
__device__ float g_m[B_ROWS];
__device__ float g_tau[B_ROWS];

// ---------------------------------------------------------------------------
// SGEMM: C = alpha * A @ op(B).
// TRANS_B = 1: B is [N, K] row-major (K contiguous)  -> C[m,n] = sum_k A[m,k]B[n,k]
// TRANS_B = 0: B is [K, N] row-major (N contiguous)  -> C[m,n] = sum_k A[m,k]B[k,n]
// 128x128 tile, BK=16, 256 threads, 8x8 per-thread microtile.
// A==nullptr or C==nullptr selects the g_logits scratch.
// ---------------------------------------------------------------------------
template <int TRANS_B>
__global__ __launch_bounds__(256) void sgemm_kernel(
    const float* __restrict__ A, const float* __restrict__ Bm,
    float* __restrict__ C, int M, int N, int K, float alpha)
{
    if (A == nullptr) A = g_logits;
    if (C == nullptr) C = g_logits;

    __shared__ float As[16][128];
    __shared__ float Bs[16][128];

    const int tid  = threadIdx.x;
    const int bn0  = blockIdx.x * 128;
    const int bm0  = blockIdx.y * 128;
    const int trow = tid >> 4;      // 0..15
    const int tcol = tid & 15;      // 0..15

    float acc[8][8];
#pragma unroll
    for (int i = 0; i < 8; i++)
#pragma unroll
        for (int j = 0; j < 8; j++) acc[i][j] = 0.f;

    const int ar = tid >> 2;          // 0..63 (row within tile, +64 for 2nd half)
    const int ac = (tid & 3) * 4;     // 0,4,8,12 (k within tile)
    const int bkr = tid >> 5;         // 0..7  (k row, +8 for 2nd half)  [NN path]
    const int bc  = (tid & 31) * 4;   // 0..124 (n col)                  [NN path]

    for (int k0 = 0; k0 < K; k0 += 16) {
        // --- load A tile (transpose into As[k][m]) ---
#pragma unroll
        for (int half = 0; half < 2; half++) {
            int r = ar + half * 64;
            float4 v = *(const float4*)&A[(size_t)(bm0 + r) * K + (k0 + ac)];
            As[ac + 0][r] = v.x; As[ac + 1][r] = v.y;
            As[ac + 2][r] = v.z; As[ac + 3][r] = v.w;
        }
        // --- load B tile into Bs[k][n] ---
        if constexpr (TRANS_B) {
#pragma unroll
            for (int half = 0; half < 2; half++) {
                int r = ar + half * 64;   // n index
                float4 v = *(const float4*)&Bm[(size_t)(bn0 + r) * K + (k0 + ac)];
                Bs[ac + 0][r] = v.x; Bs[ac + 1][r] = v.y;
                Bs[ac + 2][r] = v.z; Bs[ac + 3][r] = v.w;
            }
        } else {
#pragma unroll
            for (int half = 0; half < 2; half++) {
                int r = bkr + half * 8;   // k index
                float4 v = *(const float4*)&Bm[(size_t)(k0 + r) * N + (bn0 + bc)];
                *(float4*)&Bs[r][bc] = v;
            }
        }
        __syncthreads();

#pragma unroll
        for (int kk = 0; kk < 16; kk++) {
            float4 a0 = *(const float4*)&As[kk][trow * 8];
            float4 a1 = *(const float4*)&As[kk][trow * 8 + 4];
            float4 b0 = *(const float4*)&Bs[kk][tcol * 8];
            float4 b1 = *(const float4*)&Bs[kk][tcol * 8 + 4];
            float a[8] = {a0.x, a0.y, a0.z, a0.w, a1.x, a1.y, a1.z, a1.w};
            float b[8] = {b0.x, b0.y, b0.z, b0.w, b1.x, b1.y, b1.z, b1.w};
#pragma unroll
            for (int i = 0; i < 8; i++)
#pragma unroll
                for (int j = 0; j < 8; j++)
                    acc[i][j] = fmaf(a[i], b[j], acc[i][j]);
        }
        __syncthreads();
    }

    // epilogue
#pragma unroll
    for (int i = 0; i < 8; i++) {
        size_t row = (size_t)(bm0 + trow * 8 + i) * N + bn0 + tcol * 8;
#pragma unroll
        for (int jj = 0; jj < 2; jj++) {
            float4 v;
            v.x = alpha * acc[i][jj * 4 + 0];
            v.y = alpha * acc[i][jj * 4 + 1];
            v.z = alpha * acc[i][jj * 4 + 2];
            v.w = alpha * acc[i][jj * 4 + 3];
            *(float4*)&C[row + jj * 4] = v;
        }
    }
}

// ---------------------------------------------------------------------------
// Per-row: online (max, Z = sum e^(l-m), S = sum e^(l-m)*l) over scaled logits,
// entropy H = m + log Z - S/Z, clip-normalize, tiny MLP -> tau.
// One CTA (256 threads) per row.
// ---------------------------------------------------------------------------
__device__ __forceinline__ void mzs_combine(float& m, float& Z, float& S,
                                            float m2, float Z2, float S2)
{
    float mn = fmaxf(m, m2);
    float e1 = __expf(m - mn);
    float e2 = __expf(m2 - mn);
    Z = Z * e1 + Z2 * e2;
    S = S * e1 + S2 * e2;
    m = mn;
}

__global__ __launch_bounds__(256) void row_stats_kernel(
    const float* __restrict__ w1, const float* __restrict__ b1,
    const float* __restrict__ w2, const float* __restrict__ b2,
    float* __restrict__ ent_out, float* __restrict__ tau_out)
{
    const int row = blockIdx.x;
    const int tid = threadIdx.x;
    const float* c = g_logits + (size_t)row * NKEYS;

    float m = -INFINITY, Z = 0.f, S = 0.f;
    for (int j = tid; j < NKEYS; j += 256) {
        float l = c[j];
        if (l > m) {
            float e = __expf(m - l);
            Z *= e; S *= e; m = l;
        }
        float e = __expf(l - m);
        Z += e;
        S += e * l;
    }
    // warp reduce
#pragma unroll
    for (int off = 16; off; off >>= 1) {
        float m2 = __shfl_down_sync(0xffffffffu, m, off);
        float Z2 = __shfl_down_sync(0xffffffffu, Z, off);
        float S2 = __shfl_down_sync(0xffffffffu, S, off);
        mzs_combine(m, Z, S, m2, Z2, S2);
    }
    __shared__ float sm[8], sz[8], ss[8];
    int wid = tid >> 5, lane = tid & 31;
    if (lane == 0) { sm[wid] = m; sz[wid] = Z; ss[wid] = S; }
    __syncthreads();

    if (tid == 0) {
        m = sm[0]; Z = sz[0]; S = ss[0];
#pragma unroll
        for (int w = 1; w < 8; w++) mzs_combine(m, Z, S, sm[w], sz[w], ss[w]);

        // entropy of base-scaled softmax; -NK*EPS accounts for log(p+EPS)
        float H = m + logf(Z) - S / Z - (float)NKEYS * EPSF;
        float max_entropy = logf((float)NKEYS);
        float e = H / (max_entropy + EPSF);
        e = fminf(fmaxf(e, 0.f), 1.f);

        // MLP: 1 -> 32 (exact GELU) -> 1 (sigmoid)
        float acc2 = b2[0];
#pragma unroll
        for (int h = 0; h < NH; h++) {
            float z1 = e * w1[h] + b1[h];
            float g  = 0.5f * z1 * (1.f + erff(z1 * 0.70710678118654752f));
            acc2 += g * w2[h];
        }
        float sc  = 1.f / (1.f + expf(-acc2));
        float tau = TAU_MIN + (TAU_MAX - TAU_MIN) * sc;

        g_m[row]   = m;
        g_tau[row] = tau;
        if (ent_out) ent_out[row] = e;
        if (tau_out) tau_out[row] = tau;
    }
}

// ---------------------------------------------------------------------------
// Per-row tau-scaled softmax. One CTA per row; exp values staged in smem so
// each logit is read/exp'd once. attn_out == nullptr -> write back to scratch.
// ---------------------------------------------------------------------------
__global__ __launch_bounds__(256) void softmax_kernel(float* __restrict__ attn_out)
{
    __shared__ float sw[NKEYS];      // 16 KB
    __shared__ float sred[8];

    if (attn_out == nullptr) attn_out = g_logits;
    const int row = blockIdx.x;
    const int tid = threadIdx.x;
    const float* c = g_logits + (size_t)row * NKEYS;

    const float m    = g_m[row];
    const float itau = 1.f / (g_tau[row] + EPSF);

    float z = 0.f;
    for (int j = tid; j < NKEYS; j += 256) {
        float w = __expf((c[j] - m) * itau);
        sw[j] = w;
        z += w;
    }
#pragma unroll
    for (int off = 16; off; off >>= 1)
        z += __shfl_down_sync(0xffffffffu, z, off);
    int wid = tid >> 5, lane = tid & 31;
    if (lane == 0) sred[wid] = z;
    __syncthreads();
    if (tid == 0) {
        float t = 0.f;
#pragma unroll
        for (int w = 0; w < 8; w++) t += sred[w];
        sred[0] = 1.f / t;
    }
    __syncthreads();
    const float invz = sred[0];

    float* o = attn_out + (size_t)row * NKEYS;
    for (int j = tid; j < NKEYS; j += 256)
        o[j] = sw[j] * invz;
}

// ---------------------------------------------------------------------------
extern "C" void kernel_launch(void* const* d_in, const int* in_sizes, int n_in,
                              void* d_out, int out_size)
{
    const float* q      = (const float*)d_in[0];
    const float* keys   = (const float*)d_in[1];
    const float* values = (const float*)d_in[2];
    const float* w1     = (const float*)d_in[3];
    const float* b1     = (const float*)d_in[4];
    const float* w2     = (const float*)d_in[5];
    const float* b2     = (const float*)d_in[6];
    float* out = (float*)d_out;

    const size_t sz_o    = (size_t)B_ROWS * DV;
    const size_t sz_attn = (size_t)B_ROWS * NKEYS;
    const size_t full_sz = sz_o + sz_attn + 2 * (size_t)B_ROWS;
    const bool full = ((size_t)out_size >= full_sz);

    float* out_o    = out;
    float* out_attn = full ? out + sz_o : nullptr;           // nullptr -> scratch
    float* out_ent  = full ? out + sz_o + sz_attn : nullptr;
    float* out_tau  = full ? out_ent + B_ROWS : nullptr;

    const float base_scale = 0.044194173824159216f;          // 512^-0.5

    // 1) scaled logits -> scratch
    sgemm_kernel<1><<<dim3(NKEYS / 128, B_ROWS / 128), 256>>>(
        q, keys, nullptr, B_ROWS, NKEYS, DK, base_scale);

    // 2) per-row entropy + tau
    row_stats_kernel<<<B_ROWS, 256>>>(w1, b1, w2, b2, out_ent, out_tau);

    // 3) tau-scaled softmax -> attn weights
    softmax_kernel<<<B_ROWS, 256>>>(out_attn);

    // 4) output = attn @ values
    const float* attn_src = full ? out_attn : nullptr;       // nullptr -> scratch
    sgemm_kernel<0><<<dim3(DV / 128, B_ROWS / 128), 256>>>(
        attn_src, values, out_o, B_ROWS, DV, NKEYS, 1.0f);
}

// round 10
// speedup vs baseline: 2.2135x; 2.2135x over previous
#include <cuda_runtime.h>
#include <math.h>
#include <stdint.h>

// Problem shapes (fixed by the dataset)
#define B_ROWS 16384
#define DK     512
#define NKEYS  4096
#define DV     512
#define NH     32
#define TAU_MIN 0.1f
#define TAU_MAX 5.0f
#define EPSF    1e-8f

// Scratch (NEVER pass these from host code — host sees shadow symbols.
// All selection happens in device code via nullptr sentinels.)
__device__ float g_logits[(size_t)B_ROWS * NKEYS];
__device__ float g_vt[(size_t)DV * NKEYS];
__device__ float g_m[B_ROWS];
__device__ float g_tau[B_ROWS];

// ---------------------------------------------------------------------------
// tf32 mma.sync GEMM: C[M,N] = alpha * A[M,K] @ B[N,K]^T  (A,B both K-major)
// CTA tile 128x128, BK=16, 256 threads (8 warps as 4x2), warp tile 32x64.
// mma.sync.aligned.m16n8k8.row.col.f32.tf32.tf32.f32, fp32 accumulate.
// Sentinels: A==nullptr -> g_logits, Bm==nullptr -> g_vt, C==nullptr -> g_logits.
// ---------------------------------------------------------------------------
#define BK 16
#define LDS_STRIDE 20   // 16 + 4 pad words -> conflict-free fragment loads

__device__ __forceinline__ uint32_t f2tf32(float v) {
    uint32_t r;
    asm("cvt.rna.tf32.f32 %0, %1;" : "=r"(r) : "f"(v));
    return r;
}

__device__ __forceinline__ void mma_tf32(float* c, const uint32_t* a, const uint32_t* b) {
    asm volatile(
        "mma.sync.aligned.m16n8k8.row.col.f32.tf32.tf32.f32 "
        "{%0,%1,%2,%3}, {%4,%5,%6,%7}, {%8,%9}, {%0,%1,%2,%3};"
        : "+f"(c[0]), "+f"(c[1]), "+f"(c[2]), "+f"(c[3])
        : "r"(a[0]), "r"(a[1]), "r"(a[2]), "r"(a[3]), "r"(b[0]), "r"(b[1]));
}

__global__ __launch_bounds__(256, 2) void mma_gemm_kernel(
    const float* __restrict__ A, const float* __restrict__ Bm,
    float* __restrict__ C, int K, int ldc, float alpha)
{
    if (A == nullptr)  A  = g_logits;
    if (Bm == nullptr) Bm = g_vt;
    if (C == nullptr)  C  = g_logits;

    __shared__ uint32_t As[128 * LDS_STRIDE];
    __shared__ uint32_t Bs[128 * LDS_STRIDE];

    const int tid  = threadIdx.x;
    const int wid  = tid >> 5;
    const int lane = tid & 31;
    const int gid  = lane >> 2;       // group id 0..7
    const int tig  = lane & 3;        // thread in group 0..3
    const int m0w  = (wid >> 1) * 32; // warp m origin
    const int n0w  = (wid & 1) * 64;  // warp n origin
    const int bm0  = blockIdx.y * 128;
    const int bn0  = blockIdx.x * 128;

    // global staging: each thread 2 float4 per matrix per tile
    const int grow = tid >> 2;            // 0..63
    const int gkc  = (tid & 3) * 4;       // 0,4,8,12

    float acc[2][8][4];
#pragma unroll
    for (int mi = 0; mi < 2; mi++)
#pragma unroll
        for (int ni = 0; ni < 8; ni++)
#pragma unroll
            for (int c = 0; c < 4; c++) acc[mi][ni][c] = 0.f;

    const int niter = K / BK;
    for (int it = 0; it < niter; ++it) {
        const int k0 = it * BK;
#pragma unroll
        for (int h = 0; h < 2; h++) {
            int row = grow + h * 64;
            float4 v = *(const float4*)&A[(size_t)(bm0 + row) * K + k0 + gkc];
            uint32_t* p = &As[row * LDS_STRIDE + gkc];
            p[0] = f2tf32(v.x); p[1] = f2tf32(v.y);
            p[2] = f2tf32(v.z); p[3] = f2tf32(v.w);
        }
#pragma unroll
        for (int h = 0; h < 2; h++) {
            int row = grow + h * 64;
            float4 v = *(const float4*)&Bm[(size_t)(bn0 + row) * K + k0 + gkc];
            uint32_t* p = &Bs[row * LDS_STRIDE + gkc];
            p[0] = f2tf32(v.x); p[1] = f2tf32(v.y);
            p[2] = f2tf32(v.z); p[3] = f2tf32(v.w);
        }
        __syncthreads();

#pragma unroll
        for (int ks = 0; ks < 2; ks++) {
            const int kk = ks * 8 + tig;
            uint32_t a[2][4];
#pragma unroll
            for (int mi = 0; mi < 2; mi++) {
                int r = m0w + mi * 16 + gid;
                a[mi][0] = As[r * LDS_STRIDE + kk];
                a[mi][1] = As[(r + 8) * LDS_STRIDE + kk];
                a[mi][2] = As[r * LDS_STRIDE + kk + 4];
                a[mi][3] = As[(r + 8) * LDS_STRIDE + kk + 4];
            }
            uint32_t b[8][2];
#pragma unroll
            for (int ni = 0; ni < 8; ni++) {
                int c = n0w + ni * 8 + gid;
                b[ni][0] = Bs[c * LDS_STRIDE + kk];
                b[ni][1] = Bs[c * LDS_STRIDE + kk + 4];
            }
#pragma unroll
            for (int mi = 0; mi < 2; mi++)
#pragma unroll
                for (int ni = 0; ni < 8; ni++)
                    mma_tf32(acc[mi][ni], a[mi], b[ni]);
        }
        __syncthreads();
    }

    // epilogue
#pragma unroll
    for (int mi = 0; mi < 2; mi++) {
        const int row0 = bm0 + m0w + mi * 16 + gid;
#pragma unroll
        for (int ni = 0; ni < 8; ni++) {
            const int col = bn0 + n0w + ni * 8 + tig * 2;
            float2 v0 = make_float2(alpha * acc[mi][ni][0], alpha * acc[mi][ni][1]);
            float2 v1 = make_float2(alpha * acc[mi][ni][2], alpha * acc[mi][ni][3]);
            *(float2*)&C[(size_t)row0 * ldc + col]       = v0;
            *(float2*)&C[(size_t)(row0 + 8) * ldc + col] = v1;
        }
    }
}

// ---------------------------------------------------------------------------
// V transpose: g_vt[d, n] = V[n, d]   (g_vt resolved in device code)
// ---------------------------------------------------------------------------
__global__ void transpose_v_kernel(const float* __restrict__ V)
{
    __shared__ float t[32][33];
    const int n0 = blockIdx.x * 32;
    const int d0 = blockIdx.y * 32;
    const int x = threadIdx.x, y = threadIdx.y;
#pragma unroll
    for (int yy = y; yy < 32; yy += 8)
        t[yy][x] = V[(size_t)(n0 + yy) * DV + d0 + x];
    __syncthreads();
#pragma unroll
    for (int yy = y; yy < 32; yy += 8)
        g_vt[(size_t)(d0 + yy) * NKEYS + n0 + x] = t[x][yy];
}

// ---------------------------------------------------------------------------
// Per-row entropy + tau
// ---------------------------------------------------------------------------
__device__ __forceinline__ void mzs_combine(float& m, float& Z, float& S,
                                            float m2, float Z2, float S2)
{
    float mn = fmaxf(m, m2);
    float e1 = __expf(m - mn);
    float e2 = __expf(m2 - mn);
    Z = Z * e1 + Z2 * e2;
    S = S * e1 + S2 * e2;
    m = mn;
}

__global__ __launch_bounds__(256) void row_stats_kernel(
    const float* __restrict__ w1, const float* __restrict__ b1,
    const float* __restrict__ w2, const float* __restrict__ b2,
    float* __restrict__ ent_out, float* __restrict__ tau_out)
{
    const int row = blockIdx.x;
    const int tid = threadIdx.x;
    const float* c = g_logits + (size_t)row * NKEYS;

    float m = -INFINITY, Z = 0.f, S = 0.f;
    for (int j = tid; j < NKEYS; j += 256) {
        float l = c[j];
        if (l > m) {
            float e = __expf(m - l);
            Z *= e; S *= e; m = l;
        }
        float e = __expf(l - m);
        Z += e;
        S += e * l;
    }
#pragma unroll
    for (int off = 16; off; off >>= 1) {
        float m2 = __shfl_down_sync(0xffffffffu, m, off);
        float Z2 = __shfl_down_sync(0xffffffffu, Z, off);
        float S2 = __shfl_down_sync(0xffffffffu, S, off);
        mzs_combine(m, Z, S, m2, Z2, S2);
    }
    __shared__ float sm[8], sz[8], ss[8];
    int wid = tid >> 5, lane = tid & 31;
    if (lane == 0) { sm[wid] = m; sz[wid] = Z; ss[wid] = S; }
    __syncthreads();

    if (tid == 0) {
        m = sm[0]; Z = sz[0]; S = ss[0];
#pragma unroll
        for (int w = 1; w < 8; w++) mzs_combine(m, Z, S, sm[w], sz[w], ss[w]);

        float H = m + logf(Z) - S / Z - (float)NKEYS * EPSF;
        float max_entropy = logf((float)NKEYS);
        float e = H / (max_entropy + EPSF);
        e = fminf(fmaxf(e, 0.f), 1.f);

        float acc2 = b2[0];
#pragma unroll
        for (int h = 0; h < NH; h++) {
            float z1 = e * w1[h] + b1[h];
            float g  = 0.5f * z1 * (1.f + erff(z1 * 0.70710678118654752f));
            acc2 += g * w2[h];
        }
        float sc  = 1.f / (1.f + expf(-acc2));
        float tau = TAU_MIN + (TAU_MAX - TAU_MIN) * sc;

        g_m[row]   = m;
        g_tau[row] = tau;
        if (ent_out) ent_out[row] = e;
        if (tau_out) tau_out[row] = tau;
    }
}

// ---------------------------------------------------------------------------
// Per-row tau-scaled softmax
// ---------------------------------------------------------------------------
__global__ __launch_bounds__(256) void softmax_kernel(float* __restrict__ attn_out)
{
    __shared__ float sw[NKEYS];
    __shared__ float sred[8];

    if (attn_out == nullptr) attn_out = g_logits;
    const int row = blockIdx.x;
    const int tid = threadIdx.x;
    const float* c = g_logits + (size_t)row * NKEYS;

    const float m    = g_m[row];
    const float itau = 1.f / (g_tau[row] + EPSF);

    float z = 0.f;
    for (int j = tid; j < NKEYS; j += 256) {
        float w = __expf((c[j] - m) * itau);
        sw[j] = w;
        z += w;
    }
#pragma unroll
    for (int off = 16; off; off >>= 1)
        z += __shfl_down_sync(0xffffffffu, z, off);
    int wid = tid >> 5, lane = tid & 31;
    if (lane == 0) sred[wid] = z;
    __syncthreads();
    if (tid == 0) {
        float t = 0.f;
#pragma unroll
        for (int w = 0; w < 8; w++) t += sred[w];
        sred[0] = 1.f / t;
    }
    __syncthreads();
    const float invz = sred[0];

    float* o = attn_out + (size_t)row * NKEYS;
    for (int j = tid; j < NKEYS; j += 256)
        o[j] = sw[j] * invz;
}

// ---------------------------------------------------------------------------
extern "C" void kernel_launch(void* const* d_in, const int* in_sizes, int n_in,
                              void* d_out, int out_size)
{
    const float* q      = (const float*)d_in[0];
    const float* keys   = (const float*)d_in[1];
    const float* values = (const float*)d_in[2];
    const float* w1     = (const float*)d_in[3];
    const float* b1     = (const float*)d_in[4];
    const float* w2     = (const float*)d_in[5];
    const float* b2     = (const float*)d_in[6];
    float* out = (float*)d_out;

    const size_t sz_o    = (size_t)B_ROWS * DV;
    const size_t sz_attn = (size_t)B_ROWS * NKEYS;
    const size_t full_sz = sz_o + sz_attn + 2 * (size_t)B_ROWS;
    const bool full = ((size_t)out_size >= full_sz);

    float* out_o    = out;
    float* out_attn = full ? out + sz_o : nullptr;           // nullptr -> scratch
    float* out_ent  = full ? out + sz_o + sz_attn : nullptr;
    float* out_tau  = full ? out_ent + B_ROWS : nullptr;

    const float base_scale = 0.044194173824159216f;          // 512^-0.5

    // 0) transpose V -> g_vt (GEMM2's B operand, [DV, NK] k-major)
    transpose_v_kernel<<<dim3(NKEYS / 32, DV / 32), dim3(32, 8)>>>(values);

    // 1) scaled logits -> g_logits  (C = nullptr sentinel; device resolves)
    mma_gemm_kernel<<<dim3(NKEYS / 128, B_ROWS / 128), 256>>>(
        q, keys, /*C=*/nullptr, DK, NKEYS, base_scale);

    // 2) per-row entropy + tau
    row_stats_kernel<<<B_ROWS, 256>>>(w1, b1, w2, b2, out_ent, out_tau);

    // 3) tau-scaled softmax -> attn weights (or scratch)
    softmax_kernel<<<B_ROWS, 256>>>(out_attn);

    // 4) output = attn @ values (A = out_attn or scratch; B = g_vt sentinel)
    const float* attn_src = full ? out_attn : nullptr;       // nullptr -> scratch
    mma_gemm_kernel<<<dim3(DV / 128, B_ROWS / 128), 256>>>(
        attn_src, /*Bm=*/nullptr, out_o, NKEYS, DV, 1.0f);
}